// round 2
// baseline (speedup 1.0000x reference)
#include <cuda_runtime.h>

#define NN 100000
#define EE 1600000
#define ET 1700000   // EE + NN self loops
#define FIN 128
#define HD 64
#define CC 10

// ---- static device scratch (no dynamic allocation allowed) ----
__device__ float4 g_h[2][NN * (HD / 4)];   // two ping-pong feature buffers
__device__ float  g_inv[2][NN];            // per-node 1/||h|| for each buffer
__device__ int    g_deg[NN];
__device__ int    g_rowptr[NN + 1];
__device__ int    g_cursor[NN];
__device__ int    g_csrc[ET];
__device__ int    g_is64;                  // edge_index dtype flag

// ---------------------------------------------------------------
// dtype detection: int64 edge data (values < 2^31) has zero high words
// ---------------------------------------------------------------
__global__ void detect_kernel(const int* __restrict__ p) {
    if (threadIdx.x == 0 && blockIdx.x == 0) {
        int ornz = 0;
        for (int i = 0; i < 256; i++) ornz |= p[2 * i + 1];
        g_is64 = (ornz == 0) ? 1 : 0;
    }
}

__device__ __forceinline__ int edge_at(const void* ei, long long idx, int is64) {
    int v = is64 ? (int)((const long long*)ei)[idx] : ((const int*)ei)[idx];
    // defensive clamp (no-op when dtype detection is correct)
    v = v < 0 ? 0 : (v >= NN ? NN - 1 : v);
    return v;
}

// ---------------------------------------------------------------
// CSR build
// ---------------------------------------------------------------
__global__ void init_deg_kernel() {
    int i = blockIdx.x * blockDim.x + threadIdx.x;
    if (i < NN) g_deg[i] = 1;   // self loop pre-counted
}

__global__ void build_deg_kernel(const void* __restrict__ ei) {
    int i = blockIdx.x * blockDim.x + threadIdx.x;
    if (i < EE) {
        int is64 = g_is64;
        int d = edge_at(ei, (long long)EE + i, is64);
        atomicAdd(&g_deg[d], 1);
    }
}

// single-block exclusive scan of g_deg -> g_rowptr / g_cursor
__global__ void scan_kernel() {
    const int T = 1024;
    __shared__ int sh[T];
    int t = threadIdx.x;
    const int per = (NN + T - 1) / T;   // 98
    int lo = t * per;
    if (lo > NN) lo = NN;
    int hi = lo + per; if (hi > NN) hi = NN;
    int s = 0;
    for (int i = lo; i < hi; i++) s += g_deg[i];
    sh[t] = s;
    __syncthreads();
    // Hillis-Steele inclusive scan
    for (int off = 1; off < T; off <<= 1) {
        int v = (t >= off) ? sh[t - off] : 0;
        __syncthreads();
        sh[t] += v;
        __syncthreads();
    }
    int run = (t == 0) ? 0 : sh[t - 1];   // exclusive prefix
    for (int i = lo; i < hi; i++) {
        g_rowptr[i] = run;
        g_cursor[i] = run;
        run += g_deg[i];
    }
    if (t == T - 1) g_rowptr[NN] = run;   // == ET
}

__global__ void scatter_kernel(const void* __restrict__ ei) {
    int i = blockIdx.x * blockDim.x + threadIdx.x;
    if (i >= ET) return;
    int s, d;
    if (i < EE) {
        int is64 = g_is64;
        s = edge_at(ei, i, is64);
        d = edge_at(ei, (long long)EE + i, is64);
    } else {
        s = d = i - EE;
    }
    int pos = atomicAdd(&g_cursor[d], 1);
    if (pos >= 0 && pos < ET) g_csrc[pos] = s;
}

// ---------------------------------------------------------------
// GEMM1: h0 = relu(x @ W1 + b1), fused row-norm
// one warp handles 2 nodes, 2 outputs per lane, W1 in smem
// ---------------------------------------------------------------
__global__ void gemm1_kernel(const float* __restrict__ x,
                             const float* __restrict__ W1,
                             const float* __restrict__ b1) {
    __shared__ float ws[FIN * HD];   // 32 KB
    for (int i = threadIdx.x; i < FIN * HD; i += blockDim.x) ws[i] = W1[i];
    __syncthreads();

    int warp = threadIdx.x >> 5;
    int lane = threadIdx.x & 31;
    int n0 = (blockIdx.x * 8 + warp) * 2;
    if (n0 >= NN) return;

    const float* x0 = x + (size_t)n0 * FIN;
    float2 a0 = make_float2(0.f, 0.f);
    float2 a1 = make_float2(0.f, 0.f);

    for (int k0 = 0; k0 < FIN; k0 += 32) {
        float xv0 = x0[k0 + lane];
        float xv1 = x0[FIN + k0 + lane];
#pragma unroll
        for (int t = 0; t < 32; t++) {
            float xb0 = __shfl_sync(0xFFFFFFFFu, xv0, t);
            float xb1 = __shfl_sync(0xFFFFFFFFu, xv1, t);
            float2 w = *(const float2*)&ws[(k0 + t) * HD + 2 * lane];
            a0.x += xb0 * w.x; a0.y += xb0 * w.y;
            a1.x += xb1 * w.x; a1.y += xb1 * w.y;
        }
    }
    float2 bb = *(const float2*)&b1[2 * lane];
    a0.x = fmaxf(a0.x + bb.x, 0.f); a0.y = fmaxf(a0.y + bb.y, 0.f);
    a1.x = fmaxf(a1.x + bb.x, 0.f); a1.y = fmaxf(a1.y + bb.y, 0.f);

    float2* hout = (float2*)g_h[0];
    hout[(size_t)n0 * 32 + lane]       = a0;
    hout[(size_t)(n0 + 1) * 32 + lane] = a1;

    float sq0 = a0.x * a0.x + a0.y * a0.y;
    float sq1 = a1.x * a1.x + a1.y * a1.y;
#pragma unroll
    for (int off = 16; off; off >>= 1) {
        sq0 += __shfl_xor_sync(0xFFFFFFFFu, sq0, off);
        sq1 += __shfl_xor_sync(0xFFFFFFFFu, sq1, off);
    }
    if (lane == 0) {
        g_inv[0][n0]     = rsqrtf(fmaxf(sq0, 1e-24f));
        g_inv[0][n0 + 1] = rsqrtf(fmaxf(sq1, 1e-24f));
    }
}

// ---------------------------------------------------------------
// Fused AGNN layer: softmax attention + aggregation + next norms.
// Warp per dst node, half-warp per edge (float4/lane over 16 lanes).
// No segment-max needed: alpha = cosine in [-1,1].
// ---------------------------------------------------------------
__global__ void agnn_kernel(int cur) {
    const float4* __restrict__ h   = g_h[cur];
    const float*  __restrict__ inv = g_inv[cur];
    float4* hout   = g_h[cur ^ 1];
    float*  invout = g_inv[cur ^ 1];

    int gw = (blockIdx.x * blockDim.x + threadIdx.x) >> 5;
    if (gw >= NN) return;
    int lane = threadIdx.x & 31;
    int half = lane >> 4;       // which edge of the pair
    int fl   = lane & 15;       // feature quad index

    float4 hd   = h[(size_t)gw * 16 + fl];
    float  invd = inv[gw];
    int beg = g_rowptr[gw];
    int end = g_rowptr[gw + 1];

    float4 acc = make_float4(0.f, 0.f, 0.f, 0.f);
    float denom = 0.f;

    int iters = (end - beg + 1) >> 1;
    for (int it = 0; it < iters; it++) {
        int e = beg + 2 * it + half;
        bool valid = e < end;
        int s = valid ? g_csrc[e] : gw;
        float4 hs = h[(size_t)s * 16 + fl];
        float invs = inv[s];
        float p = hd.x * hs.x + hd.y * hs.y + hd.z * hs.z + hd.w * hs.w;
        p += __shfl_xor_sync(0xFFFFFFFFu, p, 8);
        p += __shfl_xor_sync(0xFFFFFFFFu, p, 4);
        p += __shfl_xor_sync(0xFFFFFFFFu, p, 2);
        p += __shfl_xor_sync(0xFFFFFFFFu, p, 1);
        float w = valid ? __expf(p * invd * invs) : 0.f;
        denom += w;
        acc.x += w * hs.x; acc.y += w * hs.y;
        acc.z += w * hs.z; acc.w += w * hs.w;
    }
    // combine the two half-warps
    acc.x += __shfl_xor_sync(0xFFFFFFFFu, acc.x, 16);
    acc.y += __shfl_xor_sync(0xFFFFFFFFu, acc.y, 16);
    acc.z += __shfl_xor_sync(0xFFFFFFFFu, acc.z, 16);
    acc.w += __shfl_xor_sync(0xFFFFFFFFu, acc.w, 16);
    denom += __shfl_xor_sync(0xFFFFFFFFu, denom, 16);

    float r = 1.f / fmaxf(denom, 1e-16f);
    float4 o = make_float4(acc.x * r, acc.y * r, acc.z * r, acc.w * r);

    // fused norm for next layer
    float sq = o.x * o.x + o.y * o.y + o.z * o.z + o.w * o.w;
    sq += __shfl_xor_sync(0xFFFFFFFFu, sq, 8);
    sq += __shfl_xor_sync(0xFFFFFFFFu, sq, 4);
    sq += __shfl_xor_sync(0xFFFFFFFFu, sq, 2);
    sq += __shfl_xor_sync(0xFFFFFFFFu, sq, 1);

    if (half == 0) {
        hout[(size_t)gw * 16 + fl] = o;
        if (fl == 0) invout[gw] = rsqrtf(fmaxf(sq, 1e-24f));
    }
}

// ---------------------------------------------------------------
// GEMM2 + log_softmax: thread per node
// ---------------------------------------------------------------
__global__ void gemm2_kernel(const float* __restrict__ W2,
                             const float* __restrict__ b2,
                             float* __restrict__ out, int cur) {
    __shared__ float w2s[HD * CC];
    __shared__ float b2s[CC];
    for (int i = threadIdx.x; i < HD * CC; i += blockDim.x) w2s[i] = W2[i];
    if (threadIdx.x < CC) b2s[threadIdx.x] = b2[threadIdx.x];
    __syncthreads();

    int node = blockIdx.x * blockDim.x + threadIdx.x;
    if (node >= NN) return;

    const float4* hp = (const float4*)g_h[cur] + (size_t)node * 16;
    float acc[CC];
#pragma unroll
    for (int j = 0; j < CC; j++) acc[j] = b2s[j];
#pragma unroll
    for (int k4 = 0; k4 < 16; k4++) {
        float4 hv = hp[k4];
#pragma unroll
        for (int j = 0; j < CC; j++) {
            acc[j] += hv.x * w2s[(4 * k4 + 0) * CC + j]
                    + hv.y * w2s[(4 * k4 + 1) * CC + j]
                    + hv.z * w2s[(4 * k4 + 2) * CC + j]
                    + hv.w * w2s[(4 * k4 + 3) * CC + j];
        }
    }
    float m = acc[0];
#pragma unroll
    for (int j = 1; j < CC; j++) m = fmaxf(m, acc[j]);
    float ssum = 0.f;
#pragma unroll
    for (int j = 0; j < CC; j++) ssum += __expf(acc[j] - m);
    float lse = m + logf(ssum);
#pragma unroll
    for (int j = 0; j < CC; j++) out[(size_t)node * CC + j] = acc[j] - lse;
}

// ---------------------------------------------------------------
extern "C" void kernel_launch(void* const* d_in, const int* in_sizes, int n_in,
                              void* d_out, int out_size) {
    // map inputs by element count (robust to ordering)
    const float* x = nullptr; const void* ei = nullptr;
    const float* W1 = nullptr; const float* b1 = nullptr;
    const float* W2 = nullptr; const float* b2 = nullptr;
    for (int i = 0; i < n_in; i++) {
        switch (in_sizes[i]) {
            case NN * FIN:   x  = (const float*)d_in[i]; break;
            case 2 * EE:     ei = d_in[i]; break;
            case FIN * HD:   W1 = (const float*)d_in[i]; break;
            case HD:         b1 = (const float*)d_in[i]; break;
            case HD * CC:    W2 = (const float*)d_in[i]; break;
            case CC:         b2 = (const float*)d_in[i]; break;
            default: break;
        }
    }
    float* out = (float*)d_out;

    detect_kernel<<<1, 32>>>((const int*)ei);
    init_deg_kernel<<<(NN + 255) / 256, 256>>>();
    build_deg_kernel<<<(EE + 255) / 256, 256>>>(ei);
    scan_kernel<<<1, 1024>>>();
    scatter_kernel<<<(ET + 255) / 256, 256>>>(ei);

    gemm1_kernel<<<NN / 16, 256>>>(x, W1, b1);

    for (int l = 0; l < 4; l++)
        agnn_kernel<<<(NN + 7) / 8, 256>>>(l & 1);

    gemm2_kernel<<<(NN + 255) / 256, 256>>>(W2, b2, out, 0);
}

// round 3
// speedup vs baseline: 1.2964x; 1.2964x over previous
#include <cuda_runtime.h>

#define NN 100000
#define EE 1600000
#define ET 1700000   // EE + NN self loops
#define FIN 128
#define HD 64
#define CC 10

#define SCAN_T 1024
#define SCAN_E 4
#define SCAN_CHUNK (SCAN_T * SCAN_E)                 // 4096
#define SCAN_B ((NN + SCAN_CHUNK - 1) / SCAN_CHUNK)  // 25

// ---- static device scratch (no dynamic allocation allowed) ----
__device__ float4 g_h[2][NN * (HD / 4)];   // two ping-pong feature buffers
__device__ float  g_inv[2][NN];            // per-node 1/||h|| for each buffer
__device__ int    g_deg[NN];
__device__ int    g_rowptr[NN + 1];
__device__ int    g_cursor[NN];
__device__ int    g_csrc[ET];
__device__ int    g_is64;                  // edge_index dtype flag
__device__ int    g_bsum[SCAN_B];
__device__ int    g_boff[SCAN_B];

// ---------------------------------------------------------------
// dtype detection: int64 edge data (values < 2^31) has zero high words
// ---------------------------------------------------------------
__global__ void detect_kernel(const int* __restrict__ p) {
    if (threadIdx.x == 0 && blockIdx.x == 0) {
        int ornz = 0;
        for (int i = 0; i < 256; i++) ornz |= p[2 * i + 1];
        g_is64 = (ornz == 0) ? 1 : 0;
    }
}

__device__ __forceinline__ int edge_at(const void* ei, long long idx, int is64) {
    int v = is64 ? (int)((const long long*)ei)[idx] : ((const int*)ei)[idx];
    v = v < 0 ? 0 : (v >= NN ? NN - 1 : v);   // defensive clamp (no-op normally)
    return v;
}

// ---------------------------------------------------------------
// CSR build
// ---------------------------------------------------------------
__global__ void init_deg_kernel() {
    int i = blockIdx.x * blockDim.x + threadIdx.x;
    if (i < NN) g_deg[i] = 1;   // self loop pre-counted
}

__global__ void build_deg_kernel(const void* __restrict__ ei) {
    int i = blockIdx.x * blockDim.x + threadIdx.x;
    if (i < EE) {
        int is64 = g_is64;
        int d = edge_at(ei, (long long)EE + i, is64);
        atomicAdd(&g_deg[d], 1);
    }
}

// ---- 3-phase parallel exclusive scan of g_deg -> g_rowptr/g_cursor ----
__global__ void scan_bsum_kernel() {
    __shared__ int sh[SCAN_T];
    int t = threadIdx.x;
    int base = blockIdx.x * SCAN_CHUNK + t * SCAN_E;
    int s = 0;
#pragma unroll
    for (int k = 0; k < SCAN_E; k++) {
        int i = base + k;
        if (i < NN) s += g_deg[i];
    }
    sh[t] = s;
    __syncthreads();
    // block reduce
    for (int off = SCAN_T / 2; off > 0; off >>= 1) {
        if (t < off) sh[t] += sh[t + off];
        __syncthreads();
    }
    if (t == 0) g_bsum[blockIdx.x] = sh[0];
}

__global__ void scan_boff_kernel() {
    // single warp, SCAN_B <= 32
    int t = threadIdx.x;
    int v = (t < SCAN_B) ? g_bsum[t] : 0;
    int run = 0;
#pragma unroll
    for (int off = 1; off < 32; off <<= 1) {
        int u = __shfl_up_sync(0xFFFFFFFFu, v, off);
        if (t >= off) v += u;
    }
    // v is inclusive; exclusive = v - own
    if (t < SCAN_B) {
        int own = g_bsum[t];
        g_boff[t] = v - own;
    }
    (void)run;
}

__global__ void scan_write_kernel() {
    __shared__ int sh[SCAN_T];
    int t = threadIdx.x;
    int base = blockIdx.x * SCAN_CHUNK + t * SCAN_E;
    int d[SCAN_E];
    int s = 0;
#pragma unroll
    for (int k = 0; k < SCAN_E; k++) {
        int i = base + k;
        d[k] = (i < NN) ? g_deg[i] : 0;
        s += d[k];
    }
    sh[t] = s;
    __syncthreads();
    // Hillis-Steele inclusive scan over thread sums
    for (int off = 1; off < SCAN_T; off <<= 1) {
        int v = (t >= off) ? sh[t - off] : 0;
        __syncthreads();
        sh[t] += v;
        __syncthreads();
    }
    int run = g_boff[blockIdx.x] + ((t == 0) ? 0 : sh[t - 1]);
#pragma unroll
    for (int k = 0; k < SCAN_E; k++) {
        int i = base + k;
        if (i < NN) {
            g_rowptr[i] = run;
            g_cursor[i] = run;
            run += d[k];
        }
    }
    if (blockIdx.x == 0 && t == 0) g_rowptr[NN] = ET;
}

__global__ void scatter_kernel(const void* __restrict__ ei) {
    int i = blockIdx.x * blockDim.x + threadIdx.x;
    if (i >= ET) return;
    int s, d;
    if (i < EE) {
        int is64 = g_is64;
        s = edge_at(ei, i, is64);
        d = edge_at(ei, (long long)EE + i, is64);
    } else {
        s = d = i - EE;
    }
    int pos = atomicAdd(&g_cursor[d], 1);
    if (pos >= 0 && pos < ET) g_csrc[pos] = s;
}

// ---------------------------------------------------------------
// GEMM1: h0 = relu(x @ W1 + b1), fused row-norm
// ---------------------------------------------------------------
__global__ void gemm1_kernel(const float* __restrict__ x,
                             const float* __restrict__ W1,
                             const float* __restrict__ b1) {
    __shared__ float ws[FIN * HD];   // 32 KB
    for (int i = threadIdx.x; i < FIN * HD; i += blockDim.x) ws[i] = W1[i];
    __syncthreads();

    int warp = threadIdx.x >> 5;
    int lane = threadIdx.x & 31;
    int n0 = (blockIdx.x * 8 + warp) * 2;
    if (n0 >= NN) return;

    const float* x0 = x + (size_t)n0 * FIN;
    float2 a0 = make_float2(0.f, 0.f);
    float2 a1 = make_float2(0.f, 0.f);

    for (int k0 = 0; k0 < FIN; k0 += 32) {
        float xv0 = x0[k0 + lane];
        float xv1 = x0[FIN + k0 + lane];
#pragma unroll
        for (int t = 0; t < 32; t++) {
            float xb0 = __shfl_sync(0xFFFFFFFFu, xv0, t);
            float xb1 = __shfl_sync(0xFFFFFFFFu, xv1, t);
            float2 w = *(const float2*)&ws[(k0 + t) * HD + 2 * lane];
            a0.x += xb0 * w.x; a0.y += xb0 * w.y;
            a1.x += xb1 * w.x; a1.y += xb1 * w.y;
        }
    }
    float2 bb = *(const float2*)&b1[2 * lane];
    a0.x = fmaxf(a0.x + bb.x, 0.f); a0.y = fmaxf(a0.y + bb.y, 0.f);
    a1.x = fmaxf(a1.x + bb.x, 0.f); a1.y = fmaxf(a1.y + bb.y, 0.f);

    float2* hout = (float2*)g_h[0];
    hout[(size_t)n0 * 32 + lane]       = a0;
    hout[(size_t)(n0 + 1) * 32 + lane] = a1;

    float sq0 = a0.x * a0.x + a0.y * a0.y;
    float sq1 = a1.x * a1.x + a1.y * a1.y;
#pragma unroll
    for (int off = 16; off; off >>= 1) {
        sq0 += __shfl_xor_sync(0xFFFFFFFFu, sq0, off);
        sq1 += __shfl_xor_sync(0xFFFFFFFFu, sq1, off);
    }
    if (lane == 0) {
        g_inv[0][n0]     = rsqrtf(fmaxf(sq0, 1e-24f));
        g_inv[0][n0 + 1] = rsqrtf(fmaxf(sq1, 1e-24f));
    }
}

// ---------------------------------------------------------------
// Fused AGNN layer: softmax attention + aggregation + next norms.
// ---------------------------------------------------------------
__global__ void agnn_kernel(int cur) {
    const float4* __restrict__ h   = g_h[cur];
    const float*  __restrict__ inv = g_inv[cur];
    float4* hout   = g_h[cur ^ 1];
    float*  invout = g_inv[cur ^ 1];

    int gw = (blockIdx.x * blockDim.x + threadIdx.x) >> 5;
    if (gw >= NN) return;
    int lane = threadIdx.x & 31;
    int half = lane >> 4;       // which edge of the pair
    int fl   = lane & 15;       // feature quad index

    float4 hd   = h[(size_t)gw * 16 + fl];
    float  invd = inv[gw];
    int beg = g_rowptr[gw];
    int end = g_rowptr[gw + 1];

    float4 acc = make_float4(0.f, 0.f, 0.f, 0.f);
    float denom = 0.f;

    int iters = (end - beg + 1) >> 1;
    for (int it = 0; it < iters; it++) {
        int e = beg + 2 * it + half;
        bool valid = e < end;
        int s = valid ? g_csrc[e] : gw;
        float4 hs = h[(size_t)s * 16 + fl];
        float invs = inv[s];
        float p = hd.x * hs.x + hd.y * hs.y + hd.z * hs.z + hd.w * hs.w;
        p += __shfl_xor_sync(0xFFFFFFFFu, p, 8);
        p += __shfl_xor_sync(0xFFFFFFFFu, p, 4);
        p += __shfl_xor_sync(0xFFFFFFFFu, p, 2);
        p += __shfl_xor_sync(0xFFFFFFFFu, p, 1);
        float w = valid ? __expf(p * invd * invs) : 0.f;
        denom += w;
        acc.x += w * hs.x; acc.y += w * hs.y;
        acc.z += w * hs.z; acc.w += w * hs.w;
    }
    acc.x += __shfl_xor_sync(0xFFFFFFFFu, acc.x, 16);
    acc.y += __shfl_xor_sync(0xFFFFFFFFu, acc.y, 16);
    acc.z += __shfl_xor_sync(0xFFFFFFFFu, acc.z, 16);
    acc.w += __shfl_xor_sync(0xFFFFFFFFu, acc.w, 16);
    denom += __shfl_xor_sync(0xFFFFFFFFu, denom, 16);

    float r = 1.f / fmaxf(denom, 1e-16f);
    float4 o = make_float4(acc.x * r, acc.y * r, acc.z * r, acc.w * r);

    float sq = o.x * o.x + o.y * o.y + o.z * o.z + o.w * o.w;
    sq += __shfl_xor_sync(0xFFFFFFFFu, sq, 8);
    sq += __shfl_xor_sync(0xFFFFFFFFu, sq, 4);
    sq += __shfl_xor_sync(0xFFFFFFFFu, sq, 2);
    sq += __shfl_xor_sync(0xFFFFFFFFu, sq, 1);

    if (half == 0) {
        hout[(size_t)gw * 16 + fl] = o;
        if (fl == 0) invout[gw] = rsqrtf(fmaxf(sq, 1e-24f));
    }
}

// ---------------------------------------------------------------
// GEMM2 + log_softmax: thread per node
// ---------------------------------------------------------------
__global__ void gemm2_kernel(const float* __restrict__ W2,
                             const float* __restrict__ b2,
                             float* __restrict__ out, int cur) {
    __shared__ float w2s[HD * CC];
    __shared__ float b2s[CC];
    for (int i = threadIdx.x; i < HD * CC; i += blockDim.x) w2s[i] = W2[i];
    if (threadIdx.x < CC) b2s[threadIdx.x] = b2[threadIdx.x];
    __syncthreads();

    int node = blockIdx.x * blockDim.x + threadIdx.x;
    if (node >= NN) return;

    const float4* hp = (const float4*)g_h[cur] + (size_t)node * 16;
    float acc[CC];
#pragma unroll
    for (int j = 0; j < CC; j++) acc[j] = b2s[j];
#pragma unroll
    for (int k4 = 0; k4 < 16; k4++) {
        float4 hv = hp[k4];
#pragma unroll
        for (int j = 0; j < CC; j++) {
            acc[j] += hv.x * w2s[(4 * k4 + 0) * CC + j]
                    + hv.y * w2s[(4 * k4 + 1) * CC + j]
                    + hv.z * w2s[(4 * k4 + 2) * CC + j]
                    + hv.w * w2s[(4 * k4 + 3) * CC + j];
        }
    }
    float m = acc[0];
#pragma unroll
    for (int j = 1; j < CC; j++) m = fmaxf(m, acc[j]);
    float ssum = 0.f;
#pragma unroll
    for (int j = 0; j < CC; j++) ssum += __expf(acc[j] - m);
    float lse = m + logf(ssum);
#pragma unroll
    for (int j = 0; j < CC; j++) out[(size_t)node * CC + j] = acc[j] - lse;
}

// ---------------------------------------------------------------
extern "C" void kernel_launch(void* const* d_in, const int* in_sizes, int n_in,
                              void* d_out, int out_size) {
    const float* x = nullptr; const void* ei = nullptr;
    const float* W1 = nullptr; const float* b1 = nullptr;
    const float* W2 = nullptr; const float* b2 = nullptr;
    for (int i = 0; i < n_in; i++) {
        switch (in_sizes[i]) {
            case NN * FIN:   x  = (const float*)d_in[i]; break;
            case 2 * EE:     ei = d_in[i]; break;
            case FIN * HD:   W1 = (const float*)d_in[i]; break;
            case HD:         b1 = (const float*)d_in[i]; break;
            case HD * CC:    W2 = (const float*)d_in[i]; break;
            case CC:         b2 = (const float*)d_in[i]; break;
            default: break;
        }
    }
    float* out = (float*)d_out;

    detect_kernel<<<1, 32>>>((const int*)ei);
    init_deg_kernel<<<(NN + 255) / 256, 256>>>();
    build_deg_kernel<<<(EE + 255) / 256, 256>>>(ei);
    scan_bsum_kernel<<<SCAN_B, SCAN_T>>>();
    scan_boff_kernel<<<1, 32>>>();
    scan_write_kernel<<<SCAN_B, SCAN_T>>>();
    scatter_kernel<<<(ET + 255) / 256, 256>>>(ei);

    gemm1_kernel<<<NN / 16, 256>>>(x, W1, b1);

    for (int l = 0; l < 4; l++)
        agnn_kernel<<<(NN + 7) / 8, 256>>>(l & 1);

    gemm2_kernel<<<(NN + 255) / 256, 256>>>(W2, b2, out, 0);
}

// round 4
// speedup vs baseline: 1.4561x; 1.1231x over previous
#include <cuda_runtime.h>

#define NN 100000
#define EE 1600000
#define ET 1700000   // EE + NN self loops
#define FIN 128
#define HD 64
#define CC 10

#define SCAN_T 1024
#define SCAN_E 4
#define SCAN_CHUNK (SCAN_T * SCAN_E)                 // 4096
#define SCAN_B ((NN + SCAN_CHUNK - 1) / SCAN_CHUNK)  // 25

// ---- static device scratch (no dynamic allocation allowed) ----
__device__ float4 g_h[2][NN * (HD / 4)];   // two ping-pong feature buffers
__device__ float  g_inv[2][NN];            // per-node 1/||h|| for each buffer
__device__ int    g_deg[NN];
__device__ int    g_rowptr[NN + 1];
__device__ int    g_cursor[NN];
__device__ int    g_csrc[ET];
__device__ int    g_is64;                  // edge_index dtype flag
__device__ int    g_bsum[SCAN_B];
__device__ int    g_boff[SCAN_B];

// ---------------------------------------------------------------
// dtype detection: int64 edge data (values < 2^31) has zero high words
// ---------------------------------------------------------------
__global__ void detect_kernel(const int* __restrict__ p) {
    if (threadIdx.x == 0 && blockIdx.x == 0) {
        int ornz = 0;
#pragma unroll
        for (int i = 0; i < 16; i++) ornz |= p[2 * i + 1];
        g_is64 = (ornz == 0) ? 1 : 0;
    }
}

__device__ __forceinline__ int edge_at(const void* ei, long long idx, int is64) {
    int v = is64 ? (int)((const long long*)ei)[idx] : ((const int*)ei)[idx];
    v = v < 0 ? 0 : (v >= NN ? NN - 1 : v);   // defensive clamp (no-op normally)
    return v;
}

// ---------------------------------------------------------------
// CSR build
// ---------------------------------------------------------------
__global__ void init_deg_kernel() {
    int i = blockIdx.x * blockDim.x + threadIdx.x;
    if (i < NN) g_deg[i] = 1;   // self loop pre-counted
}

__global__ void build_deg_kernel(const void* __restrict__ ei) {
    int i = blockIdx.x * blockDim.x + threadIdx.x;
    if (i < EE) {
        int is64 = g_is64;
        int d = edge_at(ei, (long long)EE + i, is64);
        atomicAdd(&g_deg[d], 1);
    }
}

// ---- 3-phase parallel exclusive scan of g_deg -> g_rowptr/g_cursor ----
__global__ void scan_bsum_kernel() {
    __shared__ int sh[SCAN_T];
    int t = threadIdx.x;
    int base = blockIdx.x * SCAN_CHUNK + t * SCAN_E;
    int s = 0;
#pragma unroll
    for (int k = 0; k < SCAN_E; k++) {
        int i = base + k;
        if (i < NN) s += g_deg[i];
    }
    sh[t] = s;
    __syncthreads();
    for (int off = SCAN_T / 2; off > 0; off >>= 1) {
        if (t < off) sh[t] += sh[t + off];
        __syncthreads();
    }
    if (t == 0) g_bsum[blockIdx.x] = sh[0];
}

__global__ void scan_boff_kernel() {
    int t = threadIdx.x;
    int v = (t < SCAN_B) ? g_bsum[t] : 0;
#pragma unroll
    for (int off = 1; off < 32; off <<= 1) {
        int u = __shfl_up_sync(0xFFFFFFFFu, v, off);
        if (t >= off) v += u;
    }
    if (t < SCAN_B) {
        int own = g_bsum[t];
        g_boff[t] = v - own;
    }
}

__global__ void scan_write_kernel() {
    __shared__ int sh[SCAN_T];
    int t = threadIdx.x;
    int base = blockIdx.x * SCAN_CHUNK + t * SCAN_E;
    int d[SCAN_E];
    int s = 0;
#pragma unroll
    for (int k = 0; k < SCAN_E; k++) {
        int i = base + k;
        d[k] = (i < NN) ? g_deg[i] : 0;
        s += d[k];
    }
    sh[t] = s;
    __syncthreads();
    for (int off = 1; off < SCAN_T; off <<= 1) {
        int v = (t >= off) ? sh[t - off] : 0;
        __syncthreads();
        sh[t] += v;
        __syncthreads();
    }
    int run = g_boff[blockIdx.x] + ((t == 0) ? 0 : sh[t - 1]);
#pragma unroll
    for (int k = 0; k < SCAN_E; k++) {
        int i = base + k;
        if (i < NN) {
            g_rowptr[i] = run;
            g_cursor[i] = run;
            run += d[k];
        }
    }
    if (blockIdx.x == 0 && t == 0) g_rowptr[NN] = ET;
}

__global__ void scatter_kernel(const void* __restrict__ ei) {
    int i = blockIdx.x * blockDim.x + threadIdx.x;
    if (i >= ET) return;
    int s, d;
    if (i < EE) {
        int is64 = g_is64;
        s = edge_at(ei, i, is64);
        d = edge_at(ei, (long long)EE + i, is64);
    } else {
        s = d = i - EE;
    }
    int pos = atomicAdd(&g_cursor[d], 1);
    if (pos >= 0 && pos < ET) g_csrc[pos] = s;
}

// ---------------------------------------------------------------
// GEMM1: h0 = relu(x @ W1 + b1), fused row-norm
// ---------------------------------------------------------------
__global__ void gemm1_kernel(const float* __restrict__ x,
                             const float* __restrict__ W1,
                             const float* __restrict__ b1) {
    __shared__ float ws[FIN * HD];   // 32 KB
    for (int i = threadIdx.x; i < FIN * HD; i += blockDim.x) ws[i] = W1[i];
    __syncthreads();

    int warp = threadIdx.x >> 5;
    int lane = threadIdx.x & 31;
    int n0 = (blockIdx.x * 8 + warp) * 2;
    if (n0 >= NN) return;

    const float* x0 = x + (size_t)n0 * FIN;
    float2 a0 = make_float2(0.f, 0.f);
    float2 a1 = make_float2(0.f, 0.f);

    for (int k0 = 0; k0 < FIN; k0 += 32) {
        float xv0 = x0[k0 + lane];
        float xv1 = x0[FIN + k0 + lane];
#pragma unroll
        for (int t = 0; t < 32; t++) {
            float xb0 = __shfl_sync(0xFFFFFFFFu, xv0, t);
            float xb1 = __shfl_sync(0xFFFFFFFFu, xv1, t);
            float2 w = *(const float2*)&ws[(k0 + t) * HD + 2 * lane];
            a0.x += xb0 * w.x; a0.y += xb0 * w.y;
            a1.x += xb1 * w.x; a1.y += xb1 * w.y;
        }
    }
    float2 bb = *(const float2*)&b1[2 * lane];
    a0.x = fmaxf(a0.x + bb.x, 0.f); a0.y = fmaxf(a0.y + bb.y, 0.f);
    a1.x = fmaxf(a1.x + bb.x, 0.f); a1.y = fmaxf(a1.y + bb.y, 0.f);

    float2* hout = (float2*)g_h[0];
    hout[(size_t)n0 * 32 + lane]       = a0;
    hout[(size_t)(n0 + 1) * 32 + lane] = a1;

    float sq0 = a0.x * a0.x + a0.y * a0.y;
    float sq1 = a1.x * a1.x + a1.y * a1.y;
#pragma unroll
    for (int off = 16; off; off >>= 1) {
        sq0 += __shfl_xor_sync(0xFFFFFFFFu, sq0, off);
        sq1 += __shfl_xor_sync(0xFFFFFFFFu, sq1, off);
    }
    if (lane == 0) {
        g_inv[0][n0]     = rsqrtf(fmaxf(sq0, 1e-24f));
        g_inv[0][n0 + 1] = rsqrtf(fmaxf(sq1, 1e-24f));
    }
}

// ---------------------------------------------------------------
// Fused AGNN layer: warp per dst, 4 edges in flight (8 lanes/edge),
// each lane covers 8 floats (2 float4) of the 64-float row.
// No segment-max needed: alpha = cosine in [-1,1].
// ---------------------------------------------------------------
__global__ void agnn_kernel(int cur) {
    const float4* __restrict__ h   = g_h[cur];
    const float*  __restrict__ inv = g_inv[cur];
    float4* hout   = g_h[cur ^ 1];
    float*  invout = g_inv[cur ^ 1];

    int gw = (blockIdx.x * blockDim.x + threadIdx.x) >> 5;
    if (gw >= NN) return;
    int lane = threadIdx.x & 31;
    int grp  = lane >> 3;       // edge slot within iteration (0..3)
    int fl   = lane & 7;        // float4-pair index (0..7)

    float4 hd0 = h[(size_t)gw * 16 + 2 * fl];
    float4 hd1 = h[(size_t)gw * 16 + 2 * fl + 1];
    float  invd = inv[gw];
    int beg = g_rowptr[gw];
    int end = g_rowptr[gw + 1];

    float4 acc0 = make_float4(0.f, 0.f, 0.f, 0.f);
    float4 acc1 = make_float4(0.f, 0.f, 0.f, 0.f);
    float denom = 0.f;

    int iters = (end - beg + 3) >> 2;
#pragma unroll 2
    for (int it = 0; it < iters; it++) {
        int e = beg + 4 * it + grp;
        bool valid = e < end;
        int s = valid ? g_csrc[e] : gw;
        float4 a = h[(size_t)s * 16 + 2 * fl];
        float4 b = h[(size_t)s * 16 + 2 * fl + 1];
        float invs = inv[s];
        float p = a.x * hd0.x + a.y * hd0.y + a.z * hd0.z + a.w * hd0.w
                + b.x * hd1.x + b.y * hd1.y + b.z * hd1.z + b.w * hd1.w;
        p += __shfl_xor_sync(0xFFFFFFFFu, p, 4);
        p += __shfl_xor_sync(0xFFFFFFFFu, p, 2);
        p += __shfl_xor_sync(0xFFFFFFFFu, p, 1);
        float w = valid ? __expf(p * invd * invs) : 0.f;
        denom += w;
        acc0.x += w * a.x; acc0.y += w * a.y; acc0.z += w * a.z; acc0.w += w * a.w;
        acc1.x += w * b.x; acc1.y += w * b.y; acc1.z += w * b.z; acc1.w += w * b.w;
    }

    // combine the 4 edge groups (lanes with same fl, different grp)
#pragma unroll
    for (int off = 8; off <= 16; off <<= 1) {
        acc0.x += __shfl_xor_sync(0xFFFFFFFFu, acc0.x, off);
        acc0.y += __shfl_xor_sync(0xFFFFFFFFu, acc0.y, off);
        acc0.z += __shfl_xor_sync(0xFFFFFFFFu, acc0.z, off);
        acc0.w += __shfl_xor_sync(0xFFFFFFFFu, acc0.w, off);
        acc1.x += __shfl_xor_sync(0xFFFFFFFFu, acc1.x, off);
        acc1.y += __shfl_xor_sync(0xFFFFFFFFu, acc1.y, off);
        acc1.z += __shfl_xor_sync(0xFFFFFFFFu, acc1.z, off);
        acc1.w += __shfl_xor_sync(0xFFFFFFFFu, acc1.w, off);
        denom  += __shfl_xor_sync(0xFFFFFFFFu, denom, off);
    }

    float r = 1.f / fmaxf(denom, 1e-16f);
    float4 o0 = make_float4(acc0.x * r, acc0.y * r, acc0.z * r, acc0.w * r);
    float4 o1 = make_float4(acc1.x * r, acc1.y * r, acc1.z * r, acc1.w * r);

    // fused norm for next layer (reduce over 8 lanes of group 0 pattern)
    float sq = o0.x * o0.x + o0.y * o0.y + o0.z * o0.z + o0.w * o0.w
             + o1.x * o1.x + o1.y * o1.y + o1.z * o1.z + o1.w * o1.w;
    sq += __shfl_xor_sync(0xFFFFFFFFu, sq, 4);
    sq += __shfl_xor_sync(0xFFFFFFFFu, sq, 2);
    sq += __shfl_xor_sync(0xFFFFFFFFu, sq, 1);

    if (grp == 0) {
        hout[(size_t)gw * 16 + 2 * fl]     = o0;
        hout[(size_t)gw * 16 + 2 * fl + 1] = o1;
        if (fl == 0) invout[gw] = rsqrtf(fmaxf(sq, 1e-24f));
    }
}

// ---------------------------------------------------------------
// GEMM2 + log_softmax: thread per node
// ---------------------------------------------------------------
__global__ void gemm2_kernel(const float* __restrict__ W2,
                             const float* __restrict__ b2,
                             float* __restrict__ out, int cur) {
    __shared__ float w2s[HD * CC];
    __shared__ float b2s[CC];
    for (int i = threadIdx.x; i < HD * CC; i += blockDim.x) w2s[i] = W2[i];
    if (threadIdx.x < CC) b2s[threadIdx.x] = b2[threadIdx.x];
    __syncthreads();

    int node = blockIdx.x * blockDim.x + threadIdx.x;
    if (node >= NN) return;

    const float4* hp = (const float4*)g_h[cur] + (size_t)node * 16;
    float acc[CC];
#pragma unroll
    for (int j = 0; j < CC; j++) acc[j] = b2s[j];
#pragma unroll
    for (int k4 = 0; k4 < 16; k4++) {
        float4 hv = hp[k4];
#pragma unroll
        for (int j = 0; j < CC; j++) {
            acc[j] += hv.x * w2s[(4 * k4 + 0) * CC + j]
                    + hv.y * w2s[(4 * k4 + 1) * CC + j]
                    + hv.z * w2s[(4 * k4 + 2) * CC + j]
                    + hv.w * w2s[(4 * k4 + 3) * CC + j];
        }
    }
    float m = acc[0];
#pragma unroll
    for (int j = 1; j < CC; j++) m = fmaxf(m, acc[j]);
    float ssum = 0.f;
#pragma unroll
    for (int j = 0; j < CC; j++) ssum += __expf(acc[j] - m);
    float lse = m + logf(ssum);
#pragma unroll
    for (int j = 0; j < CC; j++) out[(size_t)node * CC + j] = acc[j] - lse;
}

// ---------------------------------------------------------------
extern "C" void kernel_launch(void* const* d_in, const int* in_sizes, int n_in,
                              void* d_out, int out_size) {
    const float* x = nullptr; const void* ei = nullptr;
    const float* W1 = nullptr; const float* b1 = nullptr;
    const float* W2 = nullptr; const float* b2 = nullptr;
    for (int i = 0; i < n_in; i++) {
        switch (in_sizes[i]) {
            case NN * FIN:   x  = (const float*)d_in[i]; break;
            case 2 * EE:     ei = d_in[i]; break;
            case FIN * HD:   W1 = (const float*)d_in[i]; break;
            case HD:         b1 = (const float*)d_in[i]; break;
            case HD * CC:    W2 = (const float*)d_in[i]; break;
            case CC:         b2 = (const float*)d_in[i]; break;
            default: break;
        }
    }
    float* out = (float*)d_out;

    detect_kernel<<<1, 32>>>((const int*)ei);
    init_deg_kernel<<<(NN + 255) / 256, 256>>>();
    build_deg_kernel<<<(EE + 255) / 256, 256>>>(ei);
    scan_bsum_kernel<<<SCAN_B, SCAN_T>>>();
    scan_boff_kernel<<<1, 32>>>();
    scan_write_kernel<<<SCAN_B, SCAN_T>>>();
    scatter_kernel<<<(ET + 255) / 256, 256>>>(ei);

    gemm1_kernel<<<NN / 16, 256>>>(x, W1, b1);

    for (int l = 0; l < 4; l++)
        agnn_kernel<<<(NN + 7) / 8, 256>>>(l & 1);

    gemm2_kernel<<<(NN + 255) / 256, 256>>>(W2, b2, out, 0);
}